// round 15
// baseline (speedup 1.0000x reference)
#include <cuda_runtime.h>
#include <math.h>

#define BB 4
#define NN 1024
#define KNNK 16
#define N3 3072
#define NCOL 12288
#define CATC 352
#define WPSLOT 32768
#define EPSF 1e-12f

// ---- static scratch ----
__device__ __align__(16) float g_cat[BB * CATC * 3 * NN];  // [b][c][d][n]
__device__ __align__(16) float g_A [NCOL * 128];           // [cid][o]
__device__ __align__(16) float g_Bm[NCOL * 128];
__device__ __align__(16) float g_Ad[NCOL * 128];
__device__ __align__(16) float g_Bd[NCOL * 128];
__device__ __align__(16) float g_U [NCOL * 128];
__device__ __align__(16) float g_Wp[4 * WPSLOT];
__device__ __align__(16) float g_ycc[BB * 128 * 3 * NN];
__device__ __align__(16) float g_y[BB * 128 * 3];
__device__ int g_idx[BB * NN * KNNK];
__device__ unsigned int g_barcnt;
__device__ unsigned int g_bargen;

// ---- grid barrier (sense-reversing; all blocks resident at 1 block/SM) ----
__device__ __forceinline__ void gridbar() {
    __threadfence();
    __syncthreads();
    if (threadIdx.x == 0) {
        unsigned int gen = *(volatile unsigned int*)&g_bargen;
        unsigned int t = atomicAdd(&g_barcnt, 1u);
        if (t == gridDim.x - 1) {
            g_barcnt = 0;
            __threadfence();
            *(volatile unsigned int*)&g_bargen = gen + 1u;
        } else {
            while (*(volatile unsigned int*)&g_bargen == gen) __nanosleep(64);
        }
    }
    __syncthreads();
}

__device__ __forceinline__ float* out_sel(int s) {
    switch (s) {
        case 0: return g_A;
        case 1: return g_Bm;
        case 2: return g_Ad;
        default: return g_Bd;
    }
}

// ================= stage bodies (verbatim math from R14 kernels) =================

// KNN body (PROTECTED d2 rounding structure — do not change)
__device__ void knn_body(const float* __restrict__ x, int bn, float* pool) {
    float* ssq = pool;
    float* sd  = pool + NN;
    float* rv  = pool + 2 * NN;
    int*   ri  = (int*)(pool + 2 * NN + 8);
    int b = bn >> 10, n = bn & (NN - 1);
    int tid = threadIdx.x;
    const float* xb = x + (size_t)b * N3;
    for (int m = tid; m < NN; m += 256) {
        float qx = xb[m], qy = xb[NN + m], qz = xb[2*NN + m];
        ssq[m] = __fadd_rn(__fadd_rn(__fmul_rn(qx, qx), __fmul_rn(qy, qy)),
                           __fmul_rn(qz, qz));
    }
    __syncthreads();
    float px = xb[n], py = xb[NN + n], pz = xb[2*NN + n];
    float sqn = ssq[n];
    for (int m = tid; m < NN; m += 256) {
        float qx = xb[m], qy = xb[NN + m], qz = xb[2*NN + m];
        float dot = __fmaf_rn(pz, qz, __fmaf_rn(py, qy, __fmul_rn(px, qx)));
        sd[m] = __fsub_rn(__fadd_rn(sqn, ssq[m]), __fmul_rn(2.0f, dot));
    }
    __syncthreads();
    for (int k = 0; k < KNNK; k++) {
        float bv = INFINITY; int bi = 0x7fffffff;
        for (int m = tid; m < NN; m += 256) {
            float v = sd[m];
            if (v < bv || (v == bv && m < bi)) { bv = v; bi = m; }
        }
        for (int off = 16; off > 0; off >>= 1) {
            float ov = __shfl_down_sync(0xffffffffu, bv, off);
            int   oi = __shfl_down_sync(0xffffffffu, bi, off);
            if (ov < bv || (ov == bv && oi < bi)) { bv = ov; bi = oi; }
        }
        if ((tid & 31) == 0) { rv[tid >> 5] = bv; ri[tid >> 5] = bi; }
        __syncthreads();
        if (tid < 32) {
            float fv = (tid < 8) ? rv[tid] : INFINITY;
            int   fi = (tid < 8) ? ri[tid] : 0x7fffffff;
            for (int off = 4; off > 0; off >>= 1) {
                float ov = __shfl_down_sync(0xffffffffu, fv, off);
                int   oi = __shfl_down_sync(0xffffffffu, fi, off);
                if (ov < fv || (ov == fv && oi < fi)) { fv = ov; fi = oi; }
            }
            if (tid == 0) {
                g_idx[bn * KNNK + k] = fi;
                sd[fi] = INFINITY;
            }
        }
        __syncthreads();
    }
}

// weight combine body
__device__ void wcomb_body(int bid,
                           const float* W1, const float* D1,
                           const float* W2, const float* D2,
                           const float* W3, const float* D3,
                           const float* W4, const float* D4) {
    const float *W, *Wd; int Cin, Cout, o, slot;
    if (bid < 32)       { W = W1; Wd = D1; Cin = 1;   Cout = 32;  o = bid;       slot = 0; }
    else if (bid < 96)  { W = W2; Wd = D2; Cin = 32;  Cout = 64;  o = bid - 32;  slot = 1; }
    else if (bid < 224) { W = W3; Wd = D3; Cin = 64;  Cout = 128; o = bid - 96;  slot = 2; }
    else                { W = W4; Wd = D4; Cin = 128; Cout = 128; o = bid - 224; slot = 3; }
    int wcols = 2 * Cin;
    int j = threadIdx.x;
    if (j < wcols) {
        float s = 0.f;
        for (int m = 0; m < Cout; m++) s += Wd[o * Cout + m] * W[m * wcols + j];
        g_Wp[slot * WPSLOT + o * wcols + j] = s;
    }
}

// fused 4-way skinny GEMM body
__device__ void gemm4_body(int bx, int by, const float* __restrict__ Wparam,
                           int wpoff, int ldw, const float* __restrict__ xin,
                           int finoff, int Cin, size_t bstride, int Cout,
                           float* ws) {
    const int R = 8;
    int groups = Cout >> 3;
    int which = by / groups;
    int o0 = (by - which * groups) * R;
    int mode = which & 1;
    const float* W = (which & 2) ? (g_Wp + wpoff) : Wparam;
    float* OUT = out_sel(which);
    for (int t = threadIdx.x; t < R * Cin; t += 256) {
        int i = t / Cin, c = t - i * Cin;
        float w = W[(o0 + i) * ldw + c];
        if (mode) w = W[(o0 + i) * ldw + Cin + c] - w;
        ws[t] = w;
    }
    __syncthreads();
    const float* FIN = xin ? xin : (g_cat + finoff);
    int cid = (bx * 256 + threadIdx.x) * 8;
    int b = cid / N3;
    int dn = cid - b * N3;
    const float* fin = FIN + (size_t)b * bstride + dn;
    float acc[8][8];
#pragma unroll
    for (int i = 0; i < 8; i++)
#pragma unroll
        for (int j = 0; j < 8; j++) acc[i][j] = 0.f;
    float4 fa = *reinterpret_cast<const float4*>(fin);
    float4 fb = *reinterpret_cast<const float4*>(fin + 4);
#pragma unroll 2
    for (int c = 0; c < Cin; c++) {
        float4 na, nb;
        if (c + 1 < Cin) {
            const float* np = fin + (size_t)(c + 1) * N3;
            na = *reinterpret_cast<const float4*>(np);
            nb = *reinterpret_cast<const float4*>(np + 4);
        }
#pragma unroll
        for (int i = 0; i < 8; i++) {
            float w = ws[i * Cin + c];
            acc[i][0] += w * fa.x; acc[i][1] += w * fa.y;
            acc[i][2] += w * fa.z; acc[i][3] += w * fa.w;
            acc[i][4] += w * fb.x; acc[i][5] += w * fb.y;
            acc[i][6] += w * fb.z; acc[i][7] += w * fb.w;
        }
        fa = na; fb = nb;
    }
#pragma unroll
    for (int j = 0; j < 8; j++) {
        float* op = OUT + (size_t)(cid + j) * Cout + o0;
        float4 v0 = make_float4(acc[0][j], acc[1][j], acc[2][j], acc[3][j]);
        float4 v1 = make_float4(acc[4][j], acc[5][j], acc[6][j], acc[7][j]);
        *(float4*)op = v0; *(float4*)(op + 4) = v1;
    }
    __syncthreads();
}

// cc GEMM body
__device__ void ccgemm_body(int bx, int by, const float* __restrict__ Wparam,
                            float* ws) {
    const int R = 8;
    int o0 = by * R;
    for (int t = threadIdx.x; t < R * CATC; t += 256) {
        int i = t / CATC, c = t - i * CATC;
        ws[t] = Wparam[i * CATC + o0 * CATC + c];
    }
    __syncthreads();
    int cid = (bx * 256 + threadIdx.x) * 8;
    int b = cid / N3;
    int dn = cid - b * N3;
    const float* fin = g_cat + (size_t)b * ((size_t)CATC * N3) + dn;
    float acc[8][8];
#pragma unroll
    for (int i = 0; i < 8; i++)
#pragma unroll
        for (int j = 0; j < 8; j++) acc[i][j] = 0.f;
    float4 fa = *reinterpret_cast<const float4*>(fin);
    float4 fb = *reinterpret_cast<const float4*>(fin + 4);
#pragma unroll 2
    for (int c = 0; c < CATC; c++) {
        float4 na, nb;
        if (c + 1 < CATC) {
            const float* np = fin + (size_t)(c + 1) * N3;
            na = *reinterpret_cast<const float4*>(np);
            nb = *reinterpret_cast<const float4*>(np + 4);
        }
#pragma unroll
        for (int i = 0; i < 8; i++) {
            float w = ws[i * CATC + c];
            acc[i][0] += w * fa.x; acc[i][1] += w * fa.y;
            acc[i][2] += w * fa.z; acc[i][3] += w * fa.w;
            acc[i][4] += w * fb.x; acc[i][5] += w * fb.y;
            acc[i][6] += w * fb.z; acc[i][7] += w * fb.w;
        }
        fa = na; fb = nb;
    }
#pragma unroll
    for (int j = 0; j < 8; j++) {
        float* op = g_U + (size_t)(cid + j) * 128 + o0;
        float4 v0 = make_float4(acc[0][j], acc[1][j], acc[2][j], acc[3][j]);
        float4 v1 = make_float4(acc[4][j], acc[5][j], acc[6][j], acc[7][j]);
        *(float4*)op = v0; *(float4*)(op + 4) = v1;
    }
    __syncthreads();
}

// edge body (float2 version)
__device__ void edge_body(int bx, int Cout, int coff, int P) {
    int half = Cout >> 1;
    int tid = threadIdx.x;
    int p = tid / half;
    int c2 = tid - p * half;
    int bn = bx * P + p;
    int b = bn >> 10, n = bn & (NN - 1);
    const int* ip = g_idx + bn * KNNK;
    int bn0 = b * N3 + n;
    size_t sN = (size_t)NN * Cout;
    size_t pn = (size_t)bn0 * Cout + 2 * c2;
    float2 bm0 = *(const float2*)&g_Bm[pn];
    float2 bm1 = *(const float2*)&g_Bm[pn + sN];
    float2 bm2 = *(const float2*)&g_Bm[pn + 2*sN];
    float2 bd0 = *(const float2*)&g_Bd[pn];
    float2 bd1 = *(const float2*)&g_Bd[pn + sN];
    float2 bd2 = *(const float2*)&g_Bd[pn + 2*sN];
    float ax0 = 0.f, ax1 = 0.f, ax2 = 0.f;
    float bx0 = 0.f, bx1 = 0.f, bx2 = 0.f;
    for (int k = 0; k < KNNK; k++) {
        int j = ip[k];
        size_t pj = (size_t)(b * N3 + j) * Cout + 2 * c2;
        float2 A0 = *(const float2*)&g_A[pj];
        float2 A1 = *(const float2*)&g_A[pj + sN];
        float2 A2 = *(const float2*)&g_A[pj + 2*sN];
        float2 D0 = *(const float2*)&g_Ad[pj];
        float2 D1 = *(const float2*)&g_Ad[pj + sN];
        float2 D2 = *(const float2*)&g_Ad[pj + 2*sN];
        {
            float y0 = A0.x + bm0.x, y1 = A1.x + bm1.x, y2 = A2.x + bm2.x;
            float d0 = D0.x + bd0.x, d1 = D1.x + bd1.x, d2 = D2.x + bd2.x;
            float dm = fmaxf(sqrtf(d0*d0 + d1*d1 + d2*d2), EPSF);
            float k0 = d0/dm, k1 = d1/dm, k2 = d2/dm;
            float dot = y0*k0 + y1*k1 + y2*k2;
            float coef = (dot < 0.f) ? (-0.8f * dot) : 0.f;
            ax0 += y0 + coef*k0; ax1 += y1 + coef*k1; ax2 += y2 + coef*k2;
        }
        {
            float y0 = A0.y + bm0.y, y1 = A1.y + bm1.y, y2 = A2.y + bm2.y;
            float d0 = D0.y + bd0.y, d1 = D1.y + bd1.y, d2 = D2.y + bd2.y;
            float dm = fmaxf(sqrtf(d0*d0 + d1*d1 + d2*d2), EPSF);
            float k0 = d0/dm, k1 = d1/dm, k2 = d2/dm;
            float dot = y0*k0 + y1*k1 + y2*k2;
            float coef = (dot < 0.f) ? (-0.8f * dot) : 0.f;
            bx0 += y0 + coef*k0; bx1 += y1 + coef*k1; bx2 += y2 + coef*k2;
        }
    }
    const float s = 1.0f / 16.0f;
    int ch = 2 * c2;
    size_t ob = ((size_t)(b * CATC + coff + ch) * 3) * NN + n;
    g_cat[ob] = ax0 * s; g_cat[ob + NN] = ax1 * s; g_cat[ob + 2*NN] = ax2 * s;
    size_t ob2 = ob + (size_t)3 * NN;
    g_cat[ob2] = bx0 * s; g_cat[ob2 + NN] = bx1 * s; g_cat[ob2 + 2*NN] = bx2 * s;
}

// ccfused body: two points per iteration (tid>>7 selects point)
__device__ void ccfused_body(int wb, const float* __restrict__ ccD, float* pool) {
    float* sk = pool;   // [2][3]
    int tid = threadIdx.x;
    int p = tid >> 7;
    int t = tid & 127;
    int bn = wb * 2 + p;
    int b = bn >> 10, n = bn & (NN - 1);
    int w = t >> 5, lane = t & 31;
    if (w < 3) {
        int cid = b * N3 + w * NN + n;
        const float* u = g_U + (size_t)cid * 128;
        float s = 0.f;
#pragma unroll
        for (int i = 0; i < 4; i++) s += ccD[i*32 + lane] * u[i*32 + lane];
        for (int off = 16; off > 0; off >>= 1)
            s += __shfl_down_sync(0xffffffffu, s, off);
        if (lane == 0) sk[p * 3 + w] = s;
    }
    __syncthreads();
    float d0 = sk[p*3 + 0], d1 = sk[p*3 + 1], d2 = sk[p*3 + 2];
    float dm = fmaxf(sqrtf(d0*d0 + d1*d1 + d2*d2), EPSF);
    float k0 = d0/dm, k1 = d1/dm, k2 = d2/dm;
    int bn0 = b * N3 + n;
    size_t sN = (size_t)NN * 128;
    size_t pp = (size_t)bn0 * 128 + t;
    float u0 = g_U[pp], u1 = g_U[pp + sN], u2 = g_U[pp + 2*sN];
    float dot = u0*k0 + u1*k1 + u2*k2;
    float coef = (dot < 0.f) ? (-0.8f * dot) : 0.f;
    size_t ob = ((size_t)(b * 128 + t) * 3) * NN + n;
    g_ycc[ob] = u0 + coef*k0; g_ycc[ob + NN] = u1 + coef*k1; g_ycc[ob + 2*NN] = u2 + coef*k2;
    __syncthreads();
}

// reduce body
__device__ void reduce_body(int bx, float* pool) {
    float* s = pool;
    const float* p = g_ycc + (size_t)bx * NN;
    int t = threadIdx.x;
    s[t] = p[t] + p[t + 256] + p[t + 512] + p[t + 768];
    __syncthreads();
    for (int off = 128; off > 0; off >>= 1) {
        if (t < off) s[t] += s[t + off];
        __syncthreads();
    }
    if (t == 0) g_y[bx] = s[0] * (1.0f / NN);
    __syncthreads();
}

// ---- head helpers (256-thread safe; trees identical to 128-thread versions) ----
__device__ float bsum128m(float v, float* s) {
    int t = threadIdx.x;
    if (t < 128) s[t] = v;
    __syncthreads();
    for (int off = 64; off > 0; off >>= 1) {
        if (t < off) s[t] += s[t + off];
        __syncthreads();
    }
    float r = s[0]; __syncthreads();
    return r;
}
__device__ void gemm3m(float (*dst)[3], const float* W,
                       const float (*src)[3], int Cout, int Cin, int c) {
    if (c < Cout) {
        float a0 = 0.f, a1 = 0.f, a2 = 0.f;
        for (int m = 0; m < Cin; m++) {
            float w = W[c * Cin + m];
            a0 += w * src[m][0]; a1 += w * src[m][1]; a2 += w * src[m][2];
        }
        dst[c][0] = a0; dst[c][1] = a1; dst[c][2] = a2;
    }
}
__device__ void act_sqm(float (*dst)[3], const float (*x)[3],
                        const float* Wd, int C, int c) {
    if (c < C) {
        float d0 = 0.f, d1 = 0.f, d2 = 0.f;
        for (int m = 0; m < C; m++) {
            float w = Wd[c * C + m];
            d0 += w * x[m][0]; d1 += w * x[m][1]; d2 += w * x[m][2];
        }
        float dm = fmaxf(sqrtf(d0*d0 + d1*d1 + d2*d2), EPSF);
        float k0 = d0/dm, k1 = d1/dm, k2 = d2/dm;
        float dot = x[c][0]*k0 + x[c][1]*k1 + x[c][2]*k2;
        float coef = (dot < 0.f) ? (-0.8f * dot) : 0.f;
        dst[c][0] = x[c][0] + coef*k0;
        dst[c][1] = x[c][1] + coef*k1;
        dst[c][2] = x[c][2] + coef*k2;
    }
}

__device__ void head_body(int wb, float* pool,
                          const float* fcO,
                          const float* rbDin, const float* rbW0,
                          const float* rbDh,  const float* rbW1,
                          const float* rbWs,
                          const float* m0W, const float* m0D,
                          const float* m1W, const float* m1D,
                          const float* l0W, const float* l0D,
                          const float* l1W, const float* l1D,
                          const float* fimW, const float* filW,
                          float* out) {
    int b = wb >> 1;
    int branch = wb & 1;
    int c = threadIdx.x;
    float (*sy)[3]  = (float(*)[3])(pool);
    float (*syn)[3] = (float(*)[3])(pool + 384);
    float (*t0)[3]  = (float(*)[3])(pool + 768);
    float (*t1)[3]  = (float(*)[3])(pool + 1152);
    float (*t2)[3]  = (float(*)[3])(pool + 1536);
    float* sred = pool + 1920;
    float* sR   = pool + 2048;

    float y0 = 0.f, y1 = 0.f, y2 = 0.f, nc = 0.f;
    if (c < 128) {
        y0 = g_y[(b*128 + c)*3 + 0];
        y1 = g_y[(b*128 + c)*3 + 1];
        y2 = g_y[(b*128 + c)*3 + 2];
        sy[c][0] = y0; sy[c][1] = y1; sy[c][2] = y2;
        nc = sqrtf(y0*y0 + y1*y1 + y2*y2);
    }
    __syncthreads();

    if (branch == 0) {
        float ss = bsum128m(nc + EPSF, sred);
        if (c == 0) out[1060 + b] = ss * (1.0f / 128.0f) * 640.0f;
    }

    float S = bsum128m(nc * nc, sred);
    if (c < 128) {
        float nn = nc / fmaxf(sqrtf(S), EPSF);
        float invn = fmaxf(nc, EPSF);
        syn[c][0] = y0/invn*nn; syn[c][1] = y1/invn*nn; syn[c][2] = y2/invn*nn;
    }
    __syncthreads();

    if (branch == 0) {
        for (int o = 0; o < 3; o++) {
            float wo = (c < 128) ? fcO[o * 128 + c] : 0.f;
            for (int d = 0; d < 3; d++) {
                float v = (c < 128) ? (wo * syn[c][d]) : 0.f;
                float r = bsum128m(v, sred);
                if (c == 0) sR[d*3 + o] = r;
            }
        }
        __syncthreads();

        if (c == 0) {
            float X[9], Cf[9];
            float fn = 0.f;
            for (int i = 0; i < 9; i++) { X[i] = sR[i]; fn += X[i]*X[i]; }
            fn = sqrtf(fn); if (fn < 1e-20f) fn = 1e-20f;
            for (int i = 0; i < 9; i++) X[i] /= fn;
            for (int it = 0; it < 25; it++) {
                Cf[0] =  (X[4]*X[8] - X[5]*X[7]);
                Cf[1] = -(X[3]*X[8] - X[5]*X[6]);
                Cf[2] =  (X[3]*X[7] - X[4]*X[6]);
                Cf[3] = -(X[1]*X[8] - X[2]*X[7]);
                Cf[4] =  (X[0]*X[8] - X[2]*X[6]);
                Cf[5] = -(X[0]*X[7] - X[1]*X[6]);
                Cf[6] =  (X[1]*X[5] - X[2]*X[4]);
                Cf[7] = -(X[0]*X[5] - X[2]*X[3]);
                Cf[8] =  (X[0]*X[4] - X[1]*X[3]);
                float det = X[0]*Cf[0] + X[1]*Cf[1] + X[2]*Cf[2];
                float ad = fabsf(det);
                if (ad < 1e-30f) break;
                float z = 1.0f / cbrtf(ad);
                float invd = 1.0f / det;
                for (int i = 0; i < 9; i++)
                    X[i] = 0.5f * (z * X[i] + (Cf[i] * invd) / z);
            }
            for (int i = 0; i < 3; i++)
                for (int j = 0; j < 3; j++)
                    out[1024 + b*9 + i*3 + j] = X[j*3 + i];
        }

        act_sqm(t0, sy, rbDin, 128, c);
        __syncthreads();
        gemm3m(t1, rbW0, t0, 64, 128, c);
        __syncthreads();
        act_sqm(t2, t1, rbDh, 64, c);
        __syncthreads();
        if (c < 3) {
            float dx = 0.f;
            for (int m = 0; m < 64; m++) dx += rbW1[m] * t2[m][c];
            float wsv = 0.f;
            for (int m = 0; m < 128; m++) wsv += rbWs[m] * sy[m][c];
            out[1064 + b*3 + c] = (wsv + dx) * 640.0f;
        }
        __syncthreads();

        gemm3m(t0, m0W, syn, 128, 128, c); __syncthreads();
        act_sqm(t1, t0, m0D, 128, c);      __syncthreads();
        gemm3m(t0, m1W, t1, 128, 128, c);  __syncthreads();
        act_sqm(t2, t0, m1D, 128, c);      __syncthreads();
        gemm3m(t0, fimW, t2, 128, 128, c); __syncthreads();
        if (c < 128)
            out[b*128 + c] = t2[c][0]*t0[c][0] + t2[c][1]*t0[c][1] + t2[c][2]*t0[c][2];
    } else {
        gemm3m(t0, l0W, syn, 128, 128, c); __syncthreads();
        act_sqm(t1, t0, l0D, 128, c);      __syncthreads();
        gemm3m(t0, l1W, t1, 128, 128, c);  __syncthreads();
        act_sqm(t2, t0, l1D, 128, c);      __syncthreads();
        gemm3m(t0, filW, t2, 128, 128, c); __syncthreads();
        if (c < 128)
            out[512 + b*128 + c] = t2[c][0]*t0[c][0] + t2[c][1]*t0[c][1] + t2[c][2]*t0[c][2];
    }
    __syncthreads();
}

// ================= the persistent mega kernel =================
__global__ __launch_bounds__(256)
void mega_k(const float* __restrict__ x,
            const float* c1W, const float* c1D, const float* c2W, const float* c2D,
            const float* c3W, const float* c3D, const float* c4W, const float* c4D,
            const float* ccW, const float* ccD, const float* fcO,
            const float* m0W, const float* m0D, const float* m1W, const float* m1D,
            const float* l0W, const float* l0D, const float* l1W, const float* l1D,
            const float* fimW, const float* filW,
            const float* rbDin, const float* rbW0, const float* rbDh,
            const float* rbW1, const float* rbWs,
            float* out) {
    __shared__ __align__(16) float pool[2880];

    // stage 1: knn + wcomb
    for (int wb = blockIdx.x; wb < BB * NN + 352; wb += gridDim.x) {
        if (wb < BB * NN) knn_body(x, wb, pool);
        else wcomb_body(wb - BB * NN, c1W, c1D, c2W, c2D, c3W, c3D, c4W, c4D);
        __syncthreads();
    }
    gridbar();

    // layers
    const float* Ws[4]   = {c1W, c2W, c3W, c4W};
    const float* xins[4] = {x, nullptr, nullptr, nullptr};
    const int Cins[4]  = {1, 32, 64, 128};
    const int Couts[4] = {32, 64, 128, 128};
    const int finoffs[4] = {0, 0, 32 * N3, 96 * N3};
    const int coffs[4] = {0, 32, 96, 224};
    const size_t catbs = (size_t)CATC * N3;

    for (int L = 0; L < 4; L++) {
        int Cin = Cins[L], Cout = Couts[L];
        size_t bstride = (L == 0) ? (size_t)N3 : catbs;
        int gy = 4 * (Cout / 8);
        int gtot = 6 * gy;
        for (int wb = blockIdx.x; wb < gtot; wb += gridDim.x)
            gemm4_body(wb % 6, wb / 6, Ws[L], L * WPSLOT, 2 * Cin,
                       xins[L], finoffs[L], Cin, bstride, Cout, pool);
        gridbar();
        int P = 256 / (Cout / 2);
        int etot = BB * NN / P;
        for (int wb = blockIdx.x; wb < etot; wb += gridDim.x)
            edge_body(wb, Cout, coffs[L], P);
        gridbar();
    }

    // cc layer
    for (int wb = blockIdx.x; wb < 96; wb += gridDim.x)
        ccgemm_body(wb % 6, wb / 6, ccW, pool);
    gridbar();

    for (int wb = blockIdx.x; wb < BB * NN / 2; wb += gridDim.x)
        ccfused_body(wb, ccD, pool);
    gridbar();

    for (int wb = blockIdx.x; wb < BB * 128 * 3; wb += gridDim.x)
        reduce_body(wb, pool);
    gridbar();

    for (int wb = blockIdx.x; wb < BB * 2; wb += gridDim.x)
        head_body(wb, pool, fcO, rbDin, rbW0, rbDh, rbW1, rbWs,
                  m0W, m0D, m1W, m1D, l0W, l0D, l1W, l1D, fimW, filW, out);
}

extern "C" void kernel_launch(void* const* d_in, const int* in_sizes, int n_in,
                              void* d_out, int out_size) {
    const float* x    = (const float*)d_in[0];
    const float* c1W  = (const float*)d_in[2];
    const float* c1D  = (const float*)d_in[3];
    const float* c2W  = (const float*)d_in[4];
    const float* c2D  = (const float*)d_in[5];
    const float* c3W  = (const float*)d_in[6];
    const float* c3D  = (const float*)d_in[7];
    const float* c4W  = (const float*)d_in[8];
    const float* c4D  = (const float*)d_in[9];
    const float* ccW  = (const float*)d_in[10];
    const float* ccD  = (const float*)d_in[11];
    const float* fcO  = (const float*)d_in[12];
    const float* m0W  = (const float*)d_in[13];
    const float* m0D  = (const float*)d_in[14];
    const float* m1W  = (const float*)d_in[15];
    const float* m1D  = (const float*)d_in[16];
    const float* l0W  = (const float*)d_in[17];
    const float* l0D  = (const float*)d_in[18];
    const float* l1W  = (const float*)d_in[19];
    const float* l1D  = (const float*)d_in[20];
    const float* fimW = (const float*)d_in[21];
    const float* filW = (const float*)d_in[22];
    const float* rbDin= (const float*)d_in[23];
    const float* rbW0 = (const float*)d_in[24];
    const float* rbDh = (const float*)d_in[25];
    const float* rbW1 = (const float*)d_in[26];
    const float* rbWs = (const float*)d_in[27];
    float* out = (float*)d_out;

    int dev = 0, sms = 148;
    cudaGetDevice(&dev);
    cudaDeviceGetAttribute(&sms, cudaDevAttrMultiProcessorCount, dev);

    mega_k<<<sms, 256>>>(x, c1W, c1D, c2W, c2D, c3W, c3D, c4W, c4D,
                         ccW, ccD, fcO, m0W, m0D, m1W, m1D,
                         l0W, l0D, l1W, l1D, fimW, filW,
                         rbDin, rbW0, rbDh, rbW1, rbWs, out);
}

// round 16
// speedup vs baseline: 1.6377x; 1.6377x over previous
#include <cuda_runtime.h>
#include <math.h>

#define BB 4
#define NN 1024
#define KNNK 16
#define N3 3072
#define NCOL 12288
#define CATC 352
#define WPSLOT 32768
#define EPSF 1e-12f

// ---- static scratch ----
__device__ __align__(16) float g_cat[BB * CATC * 3 * NN];  // [b][c][d][n]
__device__ __align__(16) float g_A [NCOL * 128];           // [cid][o], cid=b*3N+d*N+n
__device__ __align__(16) float g_Bm[NCOL * 128];
__device__ __align__(16) float g_Ad[NCOL * 128];
__device__ __align__(16) float g_Bd[NCOL * 128];
__device__ __align__(16) float g_U [NCOL * 128];
__device__ __align__(16) float g_Wp[4 * WPSLOT];
__device__ __align__(16) float g_ycc[BB * 128 * 3 * NN];
__device__ __align__(16) float g_y[BB * 128 * 3];
__device__ int g_idx[BB * NN * KNNK];

// ---- fused KNN + weight-combine: one launch ----
// blocks [0, 4096): KNN (PROTECTED d2 rounding structure — do not change)
// blocks [4096, 4448): Wp = Wd @ W for all 4 layers
__global__ void pre_k(const float* __restrict__ x,
                      const float* __restrict__ W1, const float* __restrict__ D1,
                      const float* __restrict__ W2, const float* __restrict__ D2,
                      const float* __restrict__ W3, const float* __restrict__ D3,
                      const float* __restrict__ W4, const float* __restrict__ D4) {
    __shared__ float ssq[NN];
    __shared__ float sd[NN];
    __shared__ float rv[8];
    __shared__ int   ri[8];
    if (blockIdx.x >= BB * NN) {
        int bid = blockIdx.x - BB * NN;
        const float *W, *Wd; int Cin, Cout, o, slot;
        if (bid < 32)       { W = W1; Wd = D1; Cin = 1;   Cout = 32;  o = bid;       slot = 0; }
        else if (bid < 96)  { W = W2; Wd = D2; Cin = 32;  Cout = 64;  o = bid - 32;  slot = 1; }
        else if (bid < 224) { W = W3; Wd = D3; Cin = 64;  Cout = 128; o = bid - 96;  slot = 2; }
        else                { W = W4; Wd = D4; Cin = 128; Cout = 128; o = bid - 224; slot = 3; }
        int wcols = 2 * Cin;
        int j = threadIdx.x;
        if (j >= wcols) return;
        float s = 0.f;
        for (int m = 0; m < Cout; m++) s += Wd[o * Cout + m] * W[m * wcols + j];
        g_Wp[slot * WPSLOT + o * wcols + j] = s;
        return;
    }
    int bn = blockIdx.x;
    int b = bn >> 10, n = bn & (NN - 1);
    int tid = threadIdx.x;
    const float* xb = x + (size_t)b * N3;
    for (int m = tid; m < NN; m += 256) {
        float qx = xb[m], qy = xb[NN + m], qz = xb[2*NN + m];
        ssq[m] = __fadd_rn(__fadd_rn(__fmul_rn(qx, qx), __fmul_rn(qy, qy)),
                           __fmul_rn(qz, qz));
    }
    __syncthreads();
    float px = xb[n], py = xb[NN + n], pz = xb[2*NN + n];
    float sqn = ssq[n];
    for (int m = tid; m < NN; m += 256) {
        float qx = xb[m], qy = xb[NN + m], qz = xb[2*NN + m];
        float dot = __fmaf_rn(pz, qz, __fmaf_rn(py, qy, __fmul_rn(px, qx)));
        sd[m] = __fsub_rn(__fadd_rn(sqn, ssq[m]), __fmul_rn(2.0f, dot));
    }
    __syncthreads();
    for (int k = 0; k < KNNK; k++) {
        float bv = INFINITY; int bi = 0x7fffffff;
        for (int m = tid; m < NN; m += 256) {
            float v = sd[m];
            if (v < bv || (v == bv && m < bi)) { bv = v; bi = m; }
        }
        for (int off = 16; off > 0; off >>= 1) {
            float ov = __shfl_down_sync(0xffffffffu, bv, off);
            int   oi = __shfl_down_sync(0xffffffffu, bi, off);
            if (ov < bv || (ov == bv && oi < bi)) { bv = ov; bi = oi; }
        }
        if ((tid & 31) == 0) { rv[tid >> 5] = bv; ri[tid >> 5] = bi; }
        __syncthreads();
        if (tid < 32) {
            float fv = (tid < 8) ? rv[tid] : INFINITY;
            int   fi = (tid < 8) ? ri[tid] : 0x7fffffff;
            for (int off = 4; off > 0; off >>= 1) {
                float ov = __shfl_down_sync(0xffffffffu, fv, off);
                int   oi = __shfl_down_sync(0xffffffffu, fi, off);
                if (ov < fv || (ov == fv && oi < fi)) { fv = ov; fi = oi; }
            }
            if (tid == 0) {
                g_idx[bn * KNNK + k] = fi;
                sd[fi] = INFINITY;
            }
        }
        __syncthreads();
    }
}

// ---- output selector ----
__device__ __forceinline__ float* out_sel(int s) {
    switch (s) {
        case 0: return g_A;
        case 1: return g_Bm;
        case 2: return g_Ad;
        default: return g_Bd;
    }
}

// ---- fused 4-way skinny GEMM (unchanged from R14) ----
__global__ __launch_bounds__(256)
void gemm4_k(const float* __restrict__ Wparam, int wpoff, int ldw,
             const float* __restrict__ xin, int finoff,
             int Cin, size_t bstride, int Cout) {
    extern __shared__ float ws[];
    const int R = 8;
    int groups = Cout >> 3;
    int which = blockIdx.y / groups;          // 0..3
    int o0 = (blockIdx.y - which * groups) * R;
    int mode = which & 1;
    const float* W = (which & 2) ? (g_Wp + wpoff) : Wparam;
    float* OUT = out_sel(which);
    for (int t = threadIdx.x; t < R * Cin; t += blockDim.x) {
        int i = t / Cin, c = t - i * Cin;
        float w = W[(o0 + i) * ldw + c];
        if (mode) w = W[(o0 + i) * ldw + Cin + c] - w;
        ws[t] = w;
    }
    __syncthreads();
    const float* FIN = xin ? xin : (g_cat + finoff);
    int cid = (blockIdx.x * blockDim.x + threadIdx.x) * 8;
    int b = cid / N3;
    int dn = cid - b * N3;
    const float* fin = FIN + (size_t)b * bstride + dn;
    float acc[8][8];
#pragma unroll
    for (int i = 0; i < 8; i++)
#pragma unroll
        for (int j = 0; j < 8; j++) acc[i][j] = 0.f;
    float4 fa = *reinterpret_cast<const float4*>(fin);
    float4 fb = *reinterpret_cast<const float4*>(fin + 4);
#pragma unroll 2
    for (int c = 0; c < Cin; c++) {
        float4 na, nb;
        if (c + 1 < Cin) {
            const float* np = fin + (size_t)(c + 1) * N3;
            na = *reinterpret_cast<const float4*>(np);
            nb = *reinterpret_cast<const float4*>(np + 4);
        }
#pragma unroll
        for (int i = 0; i < 8; i++) {
            float w = ws[i * Cin + c];
            acc[i][0] += w * fa.x; acc[i][1] += w * fa.y;
            acc[i][2] += w * fa.z; acc[i][3] += w * fa.w;
            acc[i][4] += w * fb.x; acc[i][5] += w * fb.y;
            acc[i][6] += w * fb.z; acc[i][7] += w * fb.w;
        }
        fa = na; fb = nb;
    }
#pragma unroll
    for (int j = 0; j < 8; j++) {
        float* op = OUT + (size_t)(cid + j) * Cout + o0;
        float4 v0 = make_float4(acc[0][j], acc[1][j], acc[2][j], acc[3][j]);
        float4 v1 = make_float4(acc[4][j], acc[5][j], acc[6][j], acc[7][j]);
        *(float4*)op = v0; *(float4*)(op + 4) = v1;
    }
}

// ---- cc skinny GEMM (unchanged from R14) ----
__global__ __launch_bounds__(256)
void gemm_k(const float* __restrict__ Wparam,
            int ldw, int Cin, size_t bstride, int Cout) {
    extern __shared__ float ws[];
    const int R = 8;
    int o0 = blockIdx.y * R;
    for (int t = threadIdx.x; t < R * Cin; t += blockDim.x) {
        int i = t / Cin, c = t - i * Cin;
        ws[t] = Wparam[(o0 + i) * ldw + c];
    }
    __syncthreads();
    int cid = (blockIdx.x * blockDim.x + threadIdx.x) * 8;
    int b = cid / N3;
    int dn = cid - b * N3;
    const float* fin = g_cat + (size_t)b * bstride + dn;
    float acc[8][8];
#pragma unroll
    for (int i = 0; i < 8; i++)
#pragma unroll
        for (int j = 0; j < 8; j++) acc[i][j] = 0.f;
    float4 fa = *reinterpret_cast<const float4*>(fin);
    float4 fb = *reinterpret_cast<const float4*>(fin + 4);
#pragma unroll 2
    for (int c = 0; c < Cin; c++) {
        float4 na, nb;
        if (c + 1 < Cin) {
            const float* np = fin + (size_t)(c + 1) * N3;
            na = *reinterpret_cast<const float4*>(np);
            nb = *reinterpret_cast<const float4*>(np + 4);
        }
#pragma unroll
        for (int i = 0; i < 8; i++) {
            float w = ws[i * Cin + c];
            acc[i][0] += w * fa.x; acc[i][1] += w * fa.y;
            acc[i][2] += w * fa.z; acc[i][3] += w * fa.w;
            acc[i][4] += w * fb.x; acc[i][5] += w * fb.y;
            acc[i][6] += w * fb.z; acc[i][7] += w * fb.w;
        }
        fa = na; fb = nb;
    }
#pragma unroll
    for (int j = 0; j < 8; j++) {
        float* op = g_U + (size_t)(cid + j) * Cout + o0;
        float4 v0 = make_float4(acc[0][j], acc[1][j], acc[2][j], acc[3][j]);
        float4 v1 = make_float4(acc[4][j], acc[5][j], acc[6][j], acc[7][j]);
        *(float4*)op = v0; *(float4*)(op + 4) = v1;
    }
}

// ---- edge: float2 gather + vec_act (rsqrt form) + mean over K ----
__global__ void edge_k(int Cout, int coff, int P) {
    int half = Cout >> 1;
    int tid = threadIdx.x;
    int p = tid / half;
    int c2 = tid - p * half;          // channels 2*c2, 2*c2+1
    int bn = blockIdx.x * P + p;
    int b = bn >> 10, n = bn & (NN - 1);
    const int* ip = g_idx + bn * KNNK;
    int bn0 = b * N3 + n;
    size_t sN = (size_t)NN * Cout;
    size_t pn = (size_t)bn0 * Cout + 2 * c2;
    float2 bm0 = *(const float2*)&g_Bm[pn];
    float2 bm1 = *(const float2*)&g_Bm[pn + sN];
    float2 bm2 = *(const float2*)&g_Bm[pn + 2*sN];
    float2 bd0 = *(const float2*)&g_Bd[pn];
    float2 bd1 = *(const float2*)&g_Bd[pn + sN];
    float2 bd2 = *(const float2*)&g_Bd[pn + 2*sN];
    float ax0 = 0.f, ax1 = 0.f, ax2 = 0.f;
    float bx0 = 0.f, bx1 = 0.f, bx2 = 0.f;
    for (int k = 0; k < KNNK; k++) {
        int j = ip[k];
        size_t pj = (size_t)(b * N3 + j) * Cout + 2 * c2;
        float2 A0 = *(const float2*)&g_A[pj];
        float2 A1 = *(const float2*)&g_A[pj + sN];
        float2 A2 = *(const float2*)&g_A[pj + 2*sN];
        float2 D0 = *(const float2*)&g_Ad[pj];
        float2 D1 = *(const float2*)&g_Ad[pj + sN];
        float2 D2 = *(const float2*)&g_Ad[pj + 2*sN];
        {
            float y0 = A0.x + bm0.x, y1 = A1.x + bm1.x, y2 = A2.x + bm2.x;
            float d0 = D0.x + bd0.x, d1 = D1.x + bd1.x, d2 = D2.x + bd2.x;
            float s2 = d0*d0 + d1*d1 + d2*d2;
            float inv = rsqrtf(fmaxf(s2, 1e-24f));
            float dot = (y0*d0 + y1*d1 + y2*d2) * inv;
            float ce = (dot < 0.f) ? (-0.8f * dot * inv) : 0.f;
            ax0 += y0 + ce*d0; ax1 += y1 + ce*d1; ax2 += y2 + ce*d2;
        }
        {
            float y0 = A0.y + bm0.y, y1 = A1.y + bm1.y, y2 = A2.y + bm2.y;
            float d0 = D0.y + bd0.y, d1 = D1.y + bd1.y, d2 = D2.y + bd2.y;
            float s2 = d0*d0 + d1*d1 + d2*d2;
            float inv = rsqrtf(fmaxf(s2, 1e-24f));
            float dot = (y0*d0 + y1*d1 + y2*d2) * inv;
            float ce = (dot < 0.f) ? (-0.8f * dot * inv) : 0.f;
            bx0 += y0 + ce*d0; bx1 += y1 + ce*d1; bx2 += y2 + ce*d2;
        }
    }
    const float s = 1.0f / 16.0f;
    int ch = 2 * c2;
    size_t ob = ((size_t)(b * CATC + coff + ch) * 3) * NN + n;
    g_cat[ob] = ax0 * s; g_cat[ob + NN] = ax1 * s; g_cat[ob + 2*NN] = ax2 * s;
    size_t ob2 = ob + (size_t)3 * NN;
    g_cat[ob2] = bx0 * s; g_cat[ob2 + NN] = bx1 * s; g_cat[ob2 + 2*NN] = bx2 * s;
}

// ---- fused cc direction-dot + vec_act (rsqrt form) ----
__global__ void ccfused_k(const float* __restrict__ ccD) {
    __shared__ float sk[3];
    int bn = blockIdx.x;
    int b = bn >> 10, n = bn & (NN - 1);
    int tid = threadIdx.x;
    int w = tid >> 5, lane = tid & 31;
    if (w < 3) {
        int cid = b * N3 + w * NN + n;
        const float* u = g_U + (size_t)cid * 128;
        float s = 0.f;
#pragma unroll
        for (int i = 0; i < 4; i++) s += ccD[i*32 + lane] * u[i*32 + lane];
        for (int off = 16; off > 0; off >>= 1)
            s += __shfl_down_sync(0xffffffffu, s, off);
        if (lane == 0) sk[w] = s;
    }
    __syncthreads();
    float d0 = sk[0], d1 = sk[1], d2 = sk[2];
    float s2 = d0*d0 + d1*d1 + d2*d2;
    float inv = rsqrtf(fmaxf(s2, 1e-24f));
    int bn0 = b * N3 + n;
    size_t sN = (size_t)NN * 128;
    size_t p = (size_t)bn0 * 128 + tid;
    float u0 = g_U[p], u1 = g_U[p + sN], u2 = g_U[p + 2*sN];
    float dot = (u0*d0 + u1*d1 + u2*d2) * inv;
    float ce = (dot < 0.f) ? (-0.8f * dot * inv) : 0.f;
    size_t ob = ((size_t)(b * 128 + tid) * 3) * NN + n;
    g_ycc[ob] = u0 + ce*d0; g_ycc[ob + NN] = u1 + ce*d1; g_ycc[ob + 2*NN] = u2 + ce*d2;
}

// ---- mean over N ----
__global__ void reduce_k() {
    __shared__ float s[256];
    const float* p = g_ycc + (size_t)blockIdx.x * NN;
    int t = threadIdx.x;
    s[t] = p[t] + p[t + 256] + p[t + 512] + p[t + 768];
    __syncthreads();
    for (int off = 128; off > 0; off >>= 1) {
        if (t < off) s[t] += s[t + off];
        __syncthreads();
    }
    if (t == 0) g_y[blockIdx.x] = s[0] * (1.0f / NN);
}

// ---- head helpers (unchanged) ----
__device__ __forceinline__ float bsum128(float v, float* s) {
    int t = threadIdx.x;
    s[t] = v; __syncthreads();
    for (int off = 64; off > 0; off >>= 1) {
        if (t < off) s[t] += s[t + off];
        __syncthreads();
    }
    float r = s[0]; __syncthreads();
    return r;
}
__device__ __forceinline__ void gemm3(float (*dst)[3], const float* W,
                                      const float (*src)[3], int Cout, int Cin, int c) {
    if (c < Cout) {
        float a0 = 0.f, a1 = 0.f, a2 = 0.f;
        for (int m = 0; m < Cin; m++) {
            float w = W[c * Cin + m];
            a0 += w * src[m][0]; a1 += w * src[m][1]; a2 += w * src[m][2];
        }
        dst[c][0] = a0; dst[c][1] = a1; dst[c][2] = a2;
    }
}
__device__ __forceinline__ void act_sq(float (*dst)[3], const float (*x)[3],
                                       const float* Wd, int C, int c) {
    if (c < C) {
        float d0 = 0.f, d1 = 0.f, d2 = 0.f;
        for (int m = 0; m < C; m++) {
            float w = Wd[c * C + m];
            d0 += w * x[m][0]; d1 += w * x[m][1]; d2 += w * x[m][2];
        }
        float dm = fmaxf(sqrtf(d0*d0 + d1*d1 + d2*d2), EPSF);
        float k0 = d0/dm, k1 = d1/dm, k2 = d2/dm;
        float dot = x[c][0]*k0 + x[c][1]*k1 + x[c][2]*k2;
        float coef = (dot < 0.f) ? (-0.8f * dot) : 0.f;
        dst[c][0] = x[c][0] + coef*k0;
        dst[c][1] = x[c][1] + coef*k1;
        dst[c][2] = x[c][2] + coef*k2;
    }
}

// ---- head: 2 blocks per batch (unchanged from R14) ----
__global__ void head_k(const float* __restrict__ fcO,
                       const float* __restrict__ rbDin, const float* __restrict__ rbW0,
                       const float* __restrict__ rbDh,  const float* __restrict__ rbW1,
                       const float* __restrict__ rbWs,
                       const float* __restrict__ m0W, const float* __restrict__ m0D,
                       const float* __restrict__ m1W, const float* __restrict__ m1D,
                       const float* __restrict__ l0W, const float* __restrict__ l0D,
                       const float* __restrict__ l1W, const float* __restrict__ l1D,
                       const float* __restrict__ fimW, const float* __restrict__ filW,
                       float* __restrict__ out) {
    int b = blockIdx.x >> 1;
    int branch = blockIdx.x & 1;
    int c = threadIdx.x;
    __shared__ float sy[128][3], syn[128][3], t0[128][3], t1[128][3], t2[128][3];
    __shared__ float sred[128];
    __shared__ float sR[9];

    float y0 = g_y[(b*128 + c)*3 + 0];
    float y1 = g_y[(b*128 + c)*3 + 1];
    float y2 = g_y[(b*128 + c)*3 + 2];
    sy[c][0] = y0; sy[c][1] = y1; sy[c][2] = y2;
    float nc = sqrtf(y0*y0 + y1*y1 + y2*y2);
    __syncthreads();

    if (branch == 0) {
        float ss = bsum128(nc + EPSF, sred);
        if (c == 0) out[1060 + b] = ss * (1.0f / 128.0f) * 640.0f;
    }

    float S = bsum128(nc * nc, sred);
    float nn = nc / fmaxf(sqrtf(S), EPSF);
    float invn = fmaxf(nc, EPSF);
    syn[c][0] = y0/invn*nn; syn[c][1] = y1/invn*nn; syn[c][2] = y2/invn*nn;
    __syncthreads();

    if (branch == 0) {
        for (int o = 0; o < 3; o++) {
            float wo = fcO[o * 128 + c];
            for (int d = 0; d < 3; d++) {
                float r = bsum128(wo * syn[c][d], sred);
                if (c == 0) sR[d*3 + o] = r;
            }
        }
        __syncthreads();

        if (c == 0) {
            float X[9], Cf[9];
            float fn = 0.f;
            for (int i = 0; i < 9; i++) { X[i] = sR[i]; fn += X[i]*X[i]; }
            fn = sqrtf(fn); if (fn < 1e-20f) fn = 1e-20f;
            for (int i = 0; i < 9; i++) X[i] /= fn;
            for (int it = 0; it < 25; it++) {
                Cf[0] =  (X[4]*X[8] - X[5]*X[7]);
                Cf[1] = -(X[3]*X[8] - X[5]*X[6]);
                Cf[2] =  (X[3]*X[7] - X[4]*X[6]);
                Cf[3] = -(X[1]*X[8] - X[2]*X[7]);
                Cf[4] =  (X[0]*X[8] - X[2]*X[6]);
                Cf[5] = -(X[0]*X[7] - X[1]*X[6]);
                Cf[6] =  (X[1]*X[5] - X[2]*X[4]);
                Cf[7] = -(X[0]*X[5] - X[2]*X[3]);
                Cf[8] =  (X[0]*X[4] - X[1]*X[3]);
                float det = X[0]*Cf[0] + X[1]*Cf[1] + X[2]*Cf[2];
                float ad = fabsf(det);
                if (ad < 1e-30f) break;
                float z = 1.0f / cbrtf(ad);
                float invd = 1.0f / det;
                for (int i = 0; i < 9; i++)
                    X[i] = 0.5f * (z * X[i] + (Cf[i] * invd) / z);
            }
            for (int i = 0; i < 3; i++)
                for (int j = 0; j < 3; j++)
                    out[1024 + b*9 + i*3 + j] = X[j*3 + i];
        }

        act_sq(t0, sy, rbDin, 128, c);
        __syncthreads();
        gemm3(t1, rbW0, t0, 64, 128, c);
        __syncthreads();
        act_sq(t2, t1, rbDh, 64, c);
        __syncthreads();
        if (c < 3) {
            float dx = 0.f;
            for (int m = 0; m < 64; m++) dx += rbW1[m] * t2[m][c];
            float wsv = 0.f;
            for (int m = 0; m < 128; m++) wsv += rbWs[m] * sy[m][c];
            out[1064 + b*3 + c] = (wsv + dx) * 640.0f;
        }
        __syncthreads();

        gemm3(t0, m0W, syn, 128, 128, c); __syncthreads();
        act_sq(t1, t0, m0D, 128, c);      __syncthreads();
        gemm3(t0, m1W, t1, 128, 128, c);  __syncthreads();
        act_sq(t2, t0, m1D, 128, c);      __syncthreads();
        gemm3(t0, fimW, t2, 128, 128, c); __syncthreads();
        out[b*128 + c] = t2[c][0]*t0[c][0] + t2[c][1]*t0[c][1] + t2[c][2]*t0[c][2];
    } else {
        gemm3(t0, l0W, syn, 128, 128, c); __syncthreads();
        act_sq(t1, t0, l0D, 128, c);      __syncthreads();
        gemm3(t0, l1W, t1, 128, 128, c);  __syncthreads();
        act_sq(t2, t0, l1D, 128, c);      __syncthreads();
        gemm3(t0, filW, t2, 128, 128, c); __syncthreads();
        out[512 + b*128 + c] = t2[c][0]*t0[c][0] + t2[c][1]*t0[c][1] + t2[c][2]*t0[c][2];
    }
}

// ---- host-side layer driver: 2 launches per layer ----
static void run_layer(const float* W, int layer, int Cin, int Cout,
                      const float* xin, int finoff, size_t bstride, int coff) {
    int wcols = 2 * Cin;
    int wpoff = layer * WPSLOT;
    dim3 g(6, 4 * (Cout / 8));
    size_t sm = (size_t)8 * Cin * sizeof(float);
    gemm4_k<<<g, 256, sm>>>(W, wpoff, wcols, xin, finoff, Cin, bstride, Cout);
    int P = 256 / (Cout / 2);
    edge_k<<<BB * NN / P, 256>>>(Cout, coff, P);
}

extern "C" void kernel_launch(void* const* d_in, const int* in_sizes, int n_in,
                              void* d_out, int out_size) {
    const float* x    = (const float*)d_in[0];
    const float* c1W  = (const float*)d_in[2];
    const float* c1D  = (const float*)d_in[3];
    const float* c2W  = (const float*)d_in[4];
    const float* c2D  = (const float*)d_in[5];
    const float* c3W  = (const float*)d_in[6];
    const float* c3D  = (const float*)d_in[7];
    const float* c4W  = (const float*)d_in[8];
    const float* c4D  = (const float*)d_in[9];
    const float* ccW  = (const float*)d_in[10];
    const float* ccD  = (const float*)d_in[11];
    const float* fcO  = (const float*)d_in[12];
    const float* m0W  = (const float*)d_in[13];
    const float* m0D  = (const float*)d_in[14];
    const float* m1W  = (const float*)d_in[15];
    const float* m1D  = (const float*)d_in[16];
    const float* l0W  = (const float*)d_in[17];
    const float* l0D  = (const float*)d_in[18];
    const float* l1W  = (const float*)d_in[19];
    const float* l1D  = (const float*)d_in[20];
    const float* fimW = (const float*)d_in[21];
    const float* filW = (const float*)d_in[22];
    const float* rbDin= (const float*)d_in[23];
    const float* rbW0 = (const float*)d_in[24];
    const float* rbDh = (const float*)d_in[25];
    const float* rbW1 = (const float*)d_in[26];
    const float* rbWs = (const float*)d_in[27];
    float* out = (float*)d_out;

    pre_k<<<BB * NN + 352, 256>>>(x, c1W, c1D, c2W, c2D, c3W, c3D, c4W, c4D);

    size_t catbs = (size_t)CATC * N3;
    run_layer(c1W, 0, 1,   32,  x,       0,        (size_t)N3, 0);
    run_layer(c2W, 1, 32,  64,  nullptr, 0,        catbs,      32);
    run_layer(c3W, 2, 64,  128, nullptr, 32 * N3,  catbs,      96);
    run_layer(c4W, 3, 128, 128, nullptr, 96 * N3,  catbs,      224);

    // cc layer
    {
        dim3 g(6, 16);
        size_t sm = (size_t)8 * CATC * sizeof(float);
        gemm_k<<<g, 256, sm>>>(ccW, CATC, CATC, catbs, 128);
    }
    ccfused_k<<<BB * NN, 128>>>(ccD);
    reduce_k<<<BB * 128 * 3, 256>>>();

    head_k<<<BB * 2, 128>>>(fcO, rbDin, rbW0, rbDh, rbW1, rbWs,
                            m0W, m0D, m1W, m1D, l0W, l0D, l1W, l1D,
                            fimW, filW, out);
}

// round 17
// speedup vs baseline: 1.6564x; 1.0115x over previous
#include <cuda_runtime.h>
#include <math.h>

#define BB 4
#define NN 1024
#define KNNK 16
#define N3 3072
#define NCOL 12288
#define CATC 352
#define WPSLOT 32768
#define EPSF 1e-12f

// ---- static scratch ----
__device__ __align__(16) float g_cat[BB * CATC * 3 * NN];  // [b][c][d][n]
__device__ __align__(16) float g_A [NCOL * 128];           // [cid][o], cid=b*3N+d*N+n
__device__ __align__(16) float g_Bm[NCOL * 128];
__device__ __align__(16) float g_Ad[NCOL * 128];
__device__ __align__(16) float g_Bd[NCOL * 128];
__device__ __align__(16) float g_U [NCOL * 128];
__device__ __align__(16) float g_Wp[4 * WPSLOT];
__device__ __align__(16) float g_ycc[BB * 128 * 3 * NN];
__device__ __align__(16) float g_y[BB * 128 * 3];
__device__ int g_idx[BB * NN * KNNK];

// ---- fused KNN + weight-combine: one launch ----
// blocks [0, 4096): KNN (PROTECTED d2 rounding structure — do not change)
// blocks [4096, 4448): Wp = Wd @ W for all 4 layers
__global__ void pre_k(const float* __restrict__ x,
                      const float* __restrict__ W1, const float* __restrict__ D1,
                      const float* __restrict__ W2, const float* __restrict__ D2,
                      const float* __restrict__ W3, const float* __restrict__ D3,
                      const float* __restrict__ W4, const float* __restrict__ D4) {
    __shared__ float ssq[NN];
    __shared__ float sd[NN];
    __shared__ float rv[8];
    __shared__ int   ri[8];
    if (blockIdx.x >= BB * NN) {
        int bid = blockIdx.x - BB * NN;
        const float *W, *Wd; int Cin, Cout, o, slot;
        if (bid < 32)       { W = W1; Wd = D1; Cin = 1;   Cout = 32;  o = bid;       slot = 0; }
        else if (bid < 96)  { W = W2; Wd = D2; Cin = 32;  Cout = 64;  o = bid - 32;  slot = 1; }
        else if (bid < 224) { W = W3; Wd = D3; Cin = 64;  Cout = 128; o = bid - 96;  slot = 2; }
        else                { W = W4; Wd = D4; Cin = 128; Cout = 128; o = bid - 224; slot = 3; }
        int wcols = 2 * Cin;
        int j = threadIdx.x;
        if (j >= wcols) return;
        float s = 0.f;
        for (int m = 0; m < Cout; m++) s += Wd[o * Cout + m] * W[m * wcols + j];
        g_Wp[slot * WPSLOT + o * wcols + j] = s;
        return;
    }
    int bn = blockIdx.x;
    int b = bn >> 10, n = bn & (NN - 1);
    int tid = threadIdx.x;
    const float* xb = x + (size_t)b * N3;
    for (int m = tid; m < NN; m += 256) {
        float qx = xb[m], qy = xb[NN + m], qz = xb[2*NN + m];
        ssq[m] = __fadd_rn(__fadd_rn(__fmul_rn(qx, qx), __fmul_rn(qy, qy)),
                           __fmul_rn(qz, qz));
    }
    __syncthreads();
    float px = xb[n], py = xb[NN + n], pz = xb[2*NN + n];
    float sqn = ssq[n];
    for (int m = tid; m < NN; m += 256) {
        float qx = xb[m], qy = xb[NN + m], qz = xb[2*NN + m];
        float dot = __fmaf_rn(pz, qz, __fmaf_rn(py, qy, __fmul_rn(px, qx)));
        sd[m] = __fsub_rn(__fadd_rn(sqn, ssq[m]), __fmul_rn(2.0f, dot));
    }
    __syncthreads();
    for (int k = 0; k < KNNK; k++) {
        float bv = INFINITY; int bi = 0x7fffffff;
        for (int m = tid; m < NN; m += 256) {
            float v = sd[m];
            if (v < bv || (v == bv && m < bi)) { bv = v; bi = m; }
        }
        for (int off = 16; off > 0; off >>= 1) {
            float ov = __shfl_down_sync(0xffffffffu, bv, off);
            int   oi = __shfl_down_sync(0xffffffffu, bi, off);
            if (ov < bv || (ov == bv && oi < bi)) { bv = ov; bi = oi; }
        }
        if ((tid & 31) == 0) { rv[tid >> 5] = bv; ri[tid >> 5] = bi; }
        __syncthreads();
        if (tid < 32) {
            float fv = (tid < 8) ? rv[tid] : INFINITY;
            int   fi = (tid < 8) ? ri[tid] : 0x7fffffff;
            for (int off = 4; off > 0; off >>= 1) {
                float ov = __shfl_down_sync(0xffffffffu, fv, off);
                int   oi = __shfl_down_sync(0xffffffffu, fi, off);
                if (ov < fv || (ov == fv && oi < fi)) { fv = ov; fi = oi; }
            }
            if (tid == 0) {
                g_idx[bn * KNNK + k] = fi;
                sd[fi] = INFINITY;
            }
        }
        __syncthreads();
    }
}

// ---- layer 1 fully fused: Cin=1 GEMM folded into the edge pass ----
// 256 threads = 8 points x 32 channels; x loads are warp-broadcast
__global__ void edge1_k(const float* __restrict__ x, const float* __restrict__ c1W) {
    __shared__ float w1s[32], dws[32], pas[32], pbs[32];
    int tid = threadIdx.x;
    if (tid < 32) {
        float a = c1W[tid * 2], b = c1W[tid * 2 + 1];
        w1s[tid] = a; dws[tid] = b - a;
        float pA = g_Wp[tid * 2], pB = g_Wp[tid * 2 + 1];
        pas[tid] = pA; pbs[tid] = pB - pA;
    }
    __syncthreads();
    int p = tid >> 5, o = tid & 31;
    int bn = blockIdx.x * 8 + p;
    int b = bn >> 10, n = bn & (NN - 1);
    const int* ip = g_idx + bn * KNNK;
    const float* xb = x + (size_t)b * N3;
    float xn0 = xb[n], xn1 = xb[NN + n], xn2 = xb[2*NN + n];
    float W1o = w1s[o], DWo = dws[o], PAo = pas[o], PBo = pbs[o];
    float bm0 = DWo * xn0, bm1 = DWo * xn1, bm2 = DWo * xn2;
    float bd0 = PBo * xn0, bd1 = PBo * xn1, bd2 = PBo * xn2;
    float ax0 = 0.f, ax1 = 0.f, ax2 = 0.f;
    for (int k = 0; k < KNNK; k++) {
        int j = ip[k];
        float xj0 = xb[j], xj1 = xb[NN + j], xj2 = xb[2*NN + j];
        float y0 = W1o * xj0 + bm0;
        float y1 = W1o * xj1 + bm1;
        float y2 = W1o * xj2 + bm2;
        float d0 = PAo * xj0 + bd0;
        float d1 = PAo * xj1 + bd1;
        float d2 = PAo * xj2 + bd2;
        float s2 = d0*d0 + d1*d1 + d2*d2;
        float inv = rsqrtf(fmaxf(s2, 1e-24f));
        float dot = (y0*d0 + y1*d1 + y2*d2) * inv;
        float ce = (dot < 0.f) ? (-0.8f * dot * inv) : 0.f;
        ax0 += y0 + ce*d0; ax1 += y1 + ce*d1; ax2 += y2 + ce*d2;
    }
    const float s = 1.0f / 16.0f;
    size_t ob = ((size_t)(b * CATC + o) * 3) * NN + n;
    g_cat[ob] = ax0 * s; g_cat[ob + NN] = ax1 * s; g_cat[ob + 2*NN] = ax2 * s;
}

// ---- output selector ----
__device__ __forceinline__ float* out_sel(int s) {
    switch (s) {
        case 0: return g_A;
        case 1: return g_Bm;
        case 2: return g_Ad;
        default: return g_Bd;
    }
}

// ---- fused 4-way skinny GEMM (unchanged) ----
__global__ __launch_bounds__(256)
void gemm4_k(const float* __restrict__ Wparam, int wpoff, int ldw,
             const float* __restrict__ xin, int finoff,
             int Cin, size_t bstride, int Cout) {
    extern __shared__ float ws[];
    const int R = 8;
    int groups = Cout >> 3;
    int which = blockIdx.y / groups;          // 0..3
    int o0 = (blockIdx.y - which * groups) * R;
    int mode = which & 1;
    const float* W = (which & 2) ? (g_Wp + wpoff) : Wparam;
    float* OUT = out_sel(which);
    for (int t = threadIdx.x; t < R * Cin; t += blockDim.x) {
        int i = t / Cin, c = t - i * Cin;
        float w = W[(o0 + i) * ldw + c];
        if (mode) w = W[(o0 + i) * ldw + Cin + c] - w;
        ws[t] = w;
    }
    __syncthreads();
    const float* FIN = xin ? xin : (g_cat + finoff);
    int cid = (blockIdx.x * blockDim.x + threadIdx.x) * 8;
    int b = cid / N3;
    int dn = cid - b * N3;
    const float* fin = FIN + (size_t)b * bstride + dn;
    float acc[8][8];
#pragma unroll
    for (int i = 0; i < 8; i++)
#pragma unroll
        for (int j = 0; j < 8; j++) acc[i][j] = 0.f;
    float4 fa = *reinterpret_cast<const float4*>(fin);
    float4 fb = *reinterpret_cast<const float4*>(fin + 4);
#pragma unroll 2
    for (int c = 0; c < Cin; c++) {
        float4 na, nb;
        if (c + 1 < Cin) {
            const float* np = fin + (size_t)(c + 1) * N3;
            na = *reinterpret_cast<const float4*>(np);
            nb = *reinterpret_cast<const float4*>(np + 4);
        }
#pragma unroll
        for (int i = 0; i < 8; i++) {
            float w = ws[i * Cin + c];
            acc[i][0] += w * fa.x; acc[i][1] += w * fa.y;
            acc[i][2] += w * fa.z; acc[i][3] += w * fa.w;
            acc[i][4] += w * fb.x; acc[i][5] += w * fb.y;
            acc[i][6] += w * fb.z; acc[i][7] += w * fb.w;
        }
        fa = na; fb = nb;
    }
#pragma unroll
    for (int j = 0; j < 8; j++) {
        float* op = OUT + (size_t)(cid + j) * Cout + o0;
        float4 v0 = make_float4(acc[0][j], acc[1][j], acc[2][j], acc[3][j]);
        float4 v1 = make_float4(acc[4][j], acc[5][j], acc[6][j], acc[7][j]);
        *(float4*)op = v0; *(float4*)(op + 4) = v1;
    }
}

// ---- cc skinny GEMM (unchanged) ----
__global__ __launch_bounds__(256)
void gemm_k(const float* __restrict__ Wparam,
            int ldw, int Cin, size_t bstride, int Cout) {
    extern __shared__ float ws[];
    const int R = 8;
    int o0 = blockIdx.y * R;
    for (int t = threadIdx.x; t < R * Cin; t += blockDim.x) {
        int i = t / Cin, c = t - i * Cin;
        ws[t] = Wparam[(o0 + i) * ldw + c];
    }
    __syncthreads();
    int cid = (blockIdx.x * blockDim.x + threadIdx.x) * 8;
    int b = cid / N3;
    int dn = cid - b * N3;
    const float* fin = g_cat + (size_t)b * bstride + dn;
    float acc[8][8];
#pragma unroll
    for (int i = 0; i < 8; i++)
#pragma unroll
        for (int j = 0; j < 8; j++) acc[i][j] = 0.f;
    float4 fa = *reinterpret_cast<const float4*>(fin);
    float4 fb = *reinterpret_cast<const float4*>(fin + 4);
#pragma unroll 2
    for (int c = 0; c < Cin; c++) {
        float4 na, nb;
        if (c + 1 < Cin) {
            const float* np = fin + (size_t)(c + 1) * N3;
            na = *reinterpret_cast<const float4*>(np);
            nb = *reinterpret_cast<const float4*>(np + 4);
        }
#pragma unroll
        for (int i = 0; i < 8; i++) {
            float w = ws[i * Cin + c];
            acc[i][0] += w * fa.x; acc[i][1] += w * fa.y;
            acc[i][2] += w * fa.z; acc[i][3] += w * fa.w;
            acc[i][4] += w * fb.x; acc[i][5] += w * fb.y;
            acc[i][6] += w * fb.z; acc[i][7] += w * fb.w;
        }
        fa = na; fb = nb;
    }
#pragma unroll
    for (int j = 0; j < 8; j++) {
        float* op = g_U + (size_t)(cid + j) * Cout + o0;
        float4 v0 = make_float4(acc[0][j], acc[1][j], acc[2][j], acc[3][j]);
        float4 v1 = make_float4(acc[4][j], acc[5][j], acc[6][j], acc[7][j]);
        *(float4*)op = v0; *(float4*)(op + 4) = v1;
    }
}

// ---- edge: float2 gather + vec_act (rsqrt form) + mean over K ----
__global__ void edge_k(int Cout, int coff, int P) {
    int half = Cout >> 1;
    int tid = threadIdx.x;
    int p = tid / half;
    int c2 = tid - p * half;          // channels 2*c2, 2*c2+1
    int bn = blockIdx.x * P + p;
    int b = bn >> 10, n = bn & (NN - 1);
    const int* ip = g_idx + bn * KNNK;
    int bn0 = b * N3 + n;
    size_t sN = (size_t)NN * Cout;
    size_t pn = (size_t)bn0 * Cout + 2 * c2;
    float2 bm0 = *(const float2*)&g_Bm[pn];
    float2 bm1 = *(const float2*)&g_Bm[pn + sN];
    float2 bm2 = *(const float2*)&g_Bm[pn + 2*sN];
    float2 bd0 = *(const float2*)&g_Bd[pn];
    float2 bd1 = *(const float2*)&g_Bd[pn + sN];
    float2 bd2 = *(const float2*)&g_Bd[pn + 2*sN];
    float ax0 = 0.f, ax1 = 0.f, ax2 = 0.f;
    float bx0 = 0.f, bx1 = 0.f, bx2 = 0.f;
    for (int k = 0; k < KNNK; k++) {
        int j = ip[k];
        size_t pj = (size_t)(b * N3 + j) * Cout + 2 * c2;
        float2 A0 = *(const float2*)&g_A[pj];
        float2 A1 = *(const float2*)&g_A[pj + sN];
        float2 A2 = *(const float2*)&g_A[pj + 2*sN];
        float2 D0 = *(const float2*)&g_Ad[pj];
        float2 D1 = *(const float2*)&g_Ad[pj + sN];
        float2 D2 = *(const float2*)&g_Ad[pj + 2*sN];
        {
            float y0 = A0.x + bm0.x, y1 = A1.x + bm1.x, y2 = A2.x + bm2.x;
            float d0 = D0.x + bd0.x, d1 = D1.x + bd1.x, d2 = D2.x + bd2.x;
            float s2 = d0*d0 + d1*d1 + d2*d2;
            float inv = rsqrtf(fmaxf(s2, 1e-24f));
            float dot = (y0*d0 + y1*d1 + y2*d2) * inv;
            float ce = (dot < 0.f) ? (-0.8f * dot * inv) : 0.f;
            ax0 += y0 + ce*d0; ax1 += y1 + ce*d1; ax2 += y2 + ce*d2;
        }
        {
            float y0 = A0.y + bm0.y, y1 = A1.y + bm1.y, y2 = A2.y + bm2.y;
            float d0 = D0.y + bd0.y, d1 = D1.y + bd1.y, d2 = D2.y + bd2.y;
            float s2 = d0*d0 + d1*d1 + d2*d2;
            float inv = rsqrtf(fmaxf(s2, 1e-24f));
            float dot = (y0*d0 + y1*d1 + y2*d2) * inv;
            float ce = (dot < 0.f) ? (-0.8f * dot * inv) : 0.f;
            bx0 += y0 + ce*d0; bx1 += y1 + ce*d1; bx2 += y2 + ce*d2;
        }
    }
    const float s = 1.0f / 16.0f;
    int ch = 2 * c2;
    size_t ob = ((size_t)(b * CATC + coff + ch) * 3) * NN + n;
    g_cat[ob] = ax0 * s; g_cat[ob + NN] = ax1 * s; g_cat[ob + 2*NN] = ax2 * s;
    size_t ob2 = ob + (size_t)3 * NN;
    g_cat[ob2] = bx0 * s; g_cat[ob2 + NN] = bx1 * s; g_cat[ob2 + 2*NN] = bx2 * s;
}

// ---- fused cc direction-dot + vec_act (rsqrt form) ----
__global__ void ccfused_k(const float* __restrict__ ccD) {
    __shared__ float sk[3];
    int bn = blockIdx.x;
    int b = bn >> 10, n = bn & (NN - 1);
    int tid = threadIdx.x;
    int w = tid >> 5, lane = tid & 31;
    if (w < 3) {
        int cid = b * N3 + w * NN + n;
        const float* u = g_U + (size_t)cid * 128;
        float s = 0.f;
#pragma unroll
        for (int i = 0; i < 4; i++) s += ccD[i*32 + lane] * u[i*32 + lane];
        for (int off = 16; off > 0; off >>= 1)
            s += __shfl_down_sync(0xffffffffu, s, off);
        if (lane == 0) sk[w] = s;
    }
    __syncthreads();
    float d0 = sk[0], d1 = sk[1], d2 = sk[2];
    float s2 = d0*d0 + d1*d1 + d2*d2;
    float inv = rsqrtf(fmaxf(s2, 1e-24f));
    int bn0 = b * N3 + n;
    size_t sN = (size_t)NN * 128;
    size_t p = (size_t)bn0 * 128 + tid;
    float u0 = g_U[p], u1 = g_U[p + sN], u2 = g_U[p + 2*sN];
    float dot = (u0*d0 + u1*d1 + u2*d2) * inv;
    float ce = (dot < 0.f) ? (-0.8f * dot * inv) : 0.f;
    size_t ob = ((size_t)(b * 128 + tid) * 3) * NN + n;
    g_ycc[ob] = u0 + ce*d0; g_ycc[ob + NN] = u1 + ce*d1; g_ycc[ob + 2*NN] = u2 + ce*d2;
}

// ---- mean over N ----
__global__ void reduce_k() {
    __shared__ float s[256];
    const float* p = g_ycc + (size_t)blockIdx.x * NN;
    int t = threadIdx.x;
    s[t] = p[t] + p[t + 256] + p[t + 512] + p[t + 768];
    __syncthreads();
    for (int off = 128; off > 0; off >>= 1) {
        if (t < off) s[t] += s[t + off];
        __syncthreads();
    }
    if (t == 0) g_y[blockIdx.x] = s[0] * (1.0f / NN);
}

// ---- head helpers (unchanged) ----
__device__ __forceinline__ float bsum128(float v, float* s) {
    int t = threadIdx.x;
    s[t] = v; __syncthreads();
    for (int off = 64; off > 0; off >>= 1) {
        if (t < off) s[t] += s[t + off];
        __syncthreads();
    }
    float r = s[0]; __syncthreads();
    return r;
}
__device__ __forceinline__ void gemm3(float (*dst)[3], const float* W,
                                      const float (*src)[3], int Cout, int Cin, int c) {
    if (c < Cout) {
        float a0 = 0.f, a1 = 0.f, a2 = 0.f;
        for (int m = 0; m < Cin; m++) {
            float w = W[c * Cin + m];
            a0 += w * src[m][0]; a1 += w * src[m][1]; a2 += w * src[m][2];
        }
        dst[c][0] = a0; dst[c][1] = a1; dst[c][2] = a2;
    }
}
__device__ __forceinline__ void act_sq(float (*dst)[3], const float (*x)[3],
                                       const float* Wd, int C, int c) {
    if (c < C) {
        float d0 = 0.f, d1 = 0.f, d2 = 0.f;
        for (int m = 0; m < C; m++) {
            float w = Wd[c * C + m];
            d0 += w * x[m][0]; d1 += w * x[m][1]; d2 += w * x[m][2];
        }
        float dm = fmaxf(sqrtf(d0*d0 + d1*d1 + d2*d2), EPSF);
        float k0 = d0/dm, k1 = d1/dm, k2 = d2/dm;
        float dot = x[c][0]*k0 + x[c][1]*k1 + x[c][2]*k2;
        float coef = (dot < 0.f) ? (-0.8f * dot) : 0.f;
        dst[c][0] = x[c][0] + coef*k0;
        dst[c][1] = x[c][1] + coef*k1;
        dst[c][2] = x[c][2] + coef*k2;
    }
}

// ---- head: 2 blocks per batch (unchanged) ----
__global__ void head_k(const float* __restrict__ fcO,
                       const float* __restrict__ rbDin, const float* __restrict__ rbW0,
                       const float* __restrict__ rbDh,  const float* __restrict__ rbW1,
                       const float* __restrict__ rbWs,
                       const float* __restrict__ m0W, const float* __restrict__ m0D,
                       const float* __restrict__ m1W, const float* __restrict__ m1D,
                       const float* __restrict__ l0W, const float* __restrict__ l0D,
                       const float* __restrict__ l1W, const float* __restrict__ l1D,
                       const float* __restrict__ fimW, const float* __restrict__ filW,
                       float* __restrict__ out) {
    int b = blockIdx.x >> 1;
    int branch = blockIdx.x & 1;
    int c = threadIdx.x;
    __shared__ float sy[128][3], syn[128][3], t0[128][3], t1[128][3], t2[128][3];
    __shared__ float sred[128];
    __shared__ float sR[9];

    float y0 = g_y[(b*128 + c)*3 + 0];
    float y1 = g_y[(b*128 + c)*3 + 1];
    float y2 = g_y[(b*128 + c)*3 + 2];
    sy[c][0] = y0; sy[c][1] = y1; sy[c][2] = y2;
    float nc = sqrtf(y0*y0 + y1*y1 + y2*y2);
    __syncthreads();

    if (branch == 0) {
        float ss = bsum128(nc + EPSF, sred);
        if (c == 0) out[1060 + b] = ss * (1.0f / 128.0f) * 640.0f;
    }

    float S = bsum128(nc * nc, sred);
    float nn = nc / fmaxf(sqrtf(S), EPSF);
    float invn = fmaxf(nc, EPSF);
    syn[c][0] = y0/invn*nn; syn[c][1] = y1/invn*nn; syn[c][2] = y2/invn*nn;
    __syncthreads();

    if (branch == 0) {
        for (int o = 0; o < 3; o++) {
            float wo = fcO[o * 128 + c];
            for (int d = 0; d < 3; d++) {
                float r = bsum128(wo * syn[c][d], sred);
                if (c == 0) sR[d*3 + o] = r;
            }
        }
        __syncthreads();

        if (c == 0) {
            float X[9], Cf[9];
            float fn = 0.f;
            for (int i = 0; i < 9; i++) { X[i] = sR[i]; fn += X[i]*X[i]; }
            fn = sqrtf(fn); if (fn < 1e-20f) fn = 1e-20f;
            for (int i = 0; i < 9; i++) X[i] /= fn;
            for (int it = 0; it < 25; it++) {
                Cf[0] =  (X[4]*X[8] - X[5]*X[7]);
                Cf[1] = -(X[3]*X[8] - X[5]*X[6]);
                Cf[2] =  (X[3]*X[7] - X[4]*X[6]);
                Cf[3] = -(X[1]*X[8] - X[2]*X[7]);
                Cf[4] =  (X[0]*X[8] - X[2]*X[6]);
                Cf[5] = -(X[0]*X[7] - X[1]*X[6]);
                Cf[6] =  (X[1]*X[5] - X[2]*X[4]);
                Cf[7] = -(X[0]*X[5] - X[2]*X[3]);
                Cf[8] =  (X[0]*X[4] - X[1]*X[3]);
                float det = X[0]*Cf[0] + X[1]*Cf[1] + X[2]*Cf[2];
                float ad = fabsf(det);
                if (ad < 1e-30f) break;
                float z = 1.0f / cbrtf(ad);
                float invd = 1.0f / det;
                for (int i = 0; i < 9; i++)
                    X[i] = 0.5f * (z * X[i] + (Cf[i] * invd) / z);
            }
            for (int i = 0; i < 3; i++)
                for (int j = 0; j < 3; j++)
                    out[1024 + b*9 + i*3 + j] = X[j*3 + i];
        }

        act_sq(t0, sy, rbDin, 128, c);
        __syncthreads();
        gemm3(t1, rbW0, t0, 64, 128, c);
        __syncthreads();
        act_sq(t2, t1, rbDh, 64, c);
        __syncthreads();
        if (c < 3) {
            float dx = 0.f;
            for (int m = 0; m < 64; m++) dx += rbW1[m] * t2[m][c];
            float wsv = 0.f;
            for (int m = 0; m < 128; m++) wsv += rbWs[m] * sy[m][c];
            out[1064 + b*3 + c] = (wsv + dx) * 640.0f;
        }
        __syncthreads();

        gemm3(t0, m0W, syn, 128, 128, c); __syncthreads();
        act_sq(t1, t0, m0D, 128, c);      __syncthreads();
        gemm3(t0, m1W, t1, 128, 128, c);  __syncthreads();
        act_sq(t2, t0, m1D, 128, c);      __syncthreads();
        gemm3(t0, fimW, t2, 128, 128, c); __syncthreads();
        out[b*128 + c] = t2[c][0]*t0[c][0] + t2[c][1]*t0[c][1] + t2[c][2]*t0[c][2];
    } else {
        gemm3(t0, l0W, syn, 128, 128, c); __syncthreads();
        act_sq(t1, t0, l0D, 128, c);      __syncthreads();
        gemm3(t0, l1W, t1, 128, 128, c);  __syncthreads();
        act_sq(t2, t0, l1D, 128, c);      __syncthreads();
        gemm3(t0, filW, t2, 128, 128, c); __syncthreads();
        out[512 + b*128 + c] = t2[c][0]*t0[c][0] + t2[c][1]*t0[c][1] + t2[c][2]*t0[c][2];
    }
}

// ---- host-side layer driver (layers 2-4) ----
static void run_layer(const float* W, int layer, int Cin, int Cout,
                      int finoff, size_t bstride, int coff) {
    int wcols = 2 * Cin;
    int wpoff = layer * WPSLOT;
    dim3 g(6, 4 * (Cout / 8));
    size_t sm = (size_t)8 * Cin * sizeof(float);
    gemm4_k<<<g, 256, sm>>>(W, wpoff, wcols, nullptr, finoff, Cin, bstride, Cout);
    int P = 256 / (Cout / 2);
    edge_k<<<BB * NN / P, 256>>>(Cout, coff, P);
}

extern "C" void kernel_launch(void* const* d_in, const int* in_sizes, int n_in,
                              void* d_out, int out_size) {
    const float* x    = (const float*)d_in[0];
    const float* c1W  = (const float*)d_in[2];
    const float* c1D  = (const float*)d_in[3];
    const float* c2W  = (const float*)d_in[4];
    const float* c2D  = (const float*)d_in[5];
    const float* c3W  = (const float*)d_in[6];
    const float* c3D  = (const float*)d_in[7];
    const float* c4W  = (const float*)d_in[8];
    const float* c4D  = (const float*)d_in[9];
    const float* ccW  = (const float*)d_in[10];
    const float* ccD  = (const float*)d_in[11];
    const float* fcO  = (const float*)d_in[12];
    const float* m0W  = (const float*)d_in[13];
    const float* m0D  = (const float*)d_in[14];
    const float* m1W  = (const float*)d_in[15];
    const float* m1D  = (const float*)d_in[16];
    const float* l0W  = (const float*)d_in[17];
    const float* l0D  = (const float*)d_in[18];
    const float* l1W  = (const float*)d_in[19];
    const float* l1D  = (const float*)d_in[20];
    const float* fimW = (const float*)d_in[21];
    const float* filW = (const float*)d_in[22];
    const float* rbDin= (const float*)d_in[23];
    const float* rbW0 = (const float*)d_in[24];
    const float* rbDh = (const float*)d_in[25];
    const float* rbW1 = (const float*)d_in[26];
    const float* rbWs = (const float*)d_in[27];
    float* out = (float*)d_out;

    pre_k<<<BB * NN + 352, 256>>>(x, c1W, c1D, c2W, c2D, c3W, c3D, c4W, c4D);

    // layer 1: fully fused (Cin=1)
    edge1_k<<<BB * NN / 8, 256>>>(x, c1W);

    size_t catbs = (size_t)CATC * N3;
    run_layer(c2W, 1, 32,  64,  0,       catbs, 32);
    run_layer(c3W, 2, 64,  128, 32 * N3, catbs, 96);
    run_layer(c4W, 3, 128, 128, 96 * N3, catbs, 224);

    // cc layer
    {
        dim3 g(6, 16);
        size_t sm = (size_t)8 * CATC * sizeof(float);
        gemm_k<<<g, 256, sm>>>(ccW, CATC, CATC, catbs, 128);
    }
    ccfused_k<<<BB * NN, 128>>>(ccD);
    reduce_k<<<BB * 128 * 3, 256>>>();

    head_k<<<BB * 2, 128>>>(fcO, rbDin, rbW0, rbDh, rbW1, rbWs,
                            m0W, m0D, m1W, m1D, l0W, l0D, l1W, l1D,
                            fimW, filW, out);
}